// round 1
// baseline (speedup 1.0000x reference)
#include <cuda_runtime.h>
#include <math.h>

// Problem constants (from reference): B=2, S=2048, D=1024, H=16, hd=64
#define BATCH 2
#define SEQ   2048
#define DMODEL 1024
#define HEADS 16
#define HDIM  64
#define MTOT  (BATCH * SEQ)          // 4096 rows for the projection GEMMs

// Scratch (device globals -- allocation-free per harness rules)
__device__ float g_Q[BATCH * HEADS * SEQ * HDIM];   // [B,H,S,hd]
__device__ float g_K[BATCH * HEADS * SEQ * HDIM];
__device__ float g_V[BATCH * HEADS * SEQ * HDIM];
__device__ float g_O[BATCH * HEADS * SEQ * HDIM];   // attention output, head layout

// ---------------------------------------------------------------------------
// Generic projection GEMM: C[m,n] = sum_k A[m,k] * W[n,k] + bias[n]
// M=4096, N=1024, K=1024.
// aHead: A is stored [B,H,S,hd] (k -> (h,d));  else A is [M,K] contiguous.
// cHead: C written to [B,H,S,hd] (n -> (h,d)); else C is [M,N] contiguous.
// Tiles: BM=BN=64, BK=16; 16x16 threads; 4x4 microtile per thread.
// smem stored transposed (sA[k][m]) so inner-loop LDS are conflict-free .128s.
// ---------------------------------------------------------------------------
__global__ __launch_bounds__(256) void gemm_proj(
    const float* __restrict__ A, const float* __restrict__ W,
    const float* __restrict__ bias, float* __restrict__ C,
    int aHead, int cHead)
{
    const int BM = 64, BN = 64, BK = 16;
    __shared__ float sA[BK][BM];
    __shared__ float sB[BK][BN];

    const int tx = threadIdx.x;            // 0..15
    const int ty = threadIdx.y;            // 0..15
    const int tid = ty * 16 + tx;
    const int row0 = blockIdx.y * BM;
    const int col0 = blockIdx.x * BN;

    const int lr = tid >> 2;               // 0..63 : tile row for loads
    const int lc = (tid & 3) << 2;         // 0,4,8,12 : k-offset for loads

    float acc[4][4];
#pragma unroll
    for (int i = 0; i < 4; i++)
#pragma unroll
        for (int j = 0; j < 4; j++) acc[i][j] = 0.0f;

    for (int kt = 0; kt < DMODEL / BK; kt++) {
        const int k = kt * BK + lc;

        // ---- load A tile (64 rows x 16 k) ----
        {
            const int m = row0 + lr;
            const float* ap;
            if (aHead) {
                const int bb = m >> 11;          // m / SEQ
                const int ss = m & (SEQ - 1);
                const int hh = k >> 6;           // k / HDIM  (constant within the 4-float group)
                const int dd = k & (HDIM - 1);
                ap = A + ((((size_t)bb * HEADS + hh) * SEQ + ss) * HDIM + dd);
            } else {
                ap = A + (size_t)m * DMODEL + k;
            }
            const float4 av = *reinterpret_cast<const float4*>(ap);
            sA[lc + 0][lr] = av.x;
            sA[lc + 1][lr] = av.y;
            sA[lc + 2][lr] = av.z;
            sA[lc + 3][lr] = av.w;
        }
        // ---- load W tile (64 n-rows x 16 k) ----
        {
            const int n = col0 + lr;
            const float4 wv = *reinterpret_cast<const float4*>(W + (size_t)n * DMODEL + k);
            sB[lc + 0][lr] = wv.x;
            sB[lc + 1][lr] = wv.y;
            sB[lc + 2][lr] = wv.z;
            sB[lc + 3][lr] = wv.w;
        }
        __syncthreads();

#pragma unroll
        for (int kk = 0; kk < BK; kk++) {
            const float4 a4 = *reinterpret_cast<const float4*>(&sA[kk][ty << 2]);
            const float4 b4 = *reinterpret_cast<const float4*>(&sB[kk][tx << 2]);
            const float ar[4] = {a4.x, a4.y, a4.z, a4.w};
            const float br[4] = {b4.x, b4.y, b4.z, b4.w};
#pragma unroll
            for (int i = 0; i < 4; i++)
#pragma unroll
                for (int j = 0; j < 4; j++) acc[i][j] += ar[i] * br[j];
        }
        __syncthreads();
    }

    // ---- epilogue ----
#pragma unroll
    for (int i = 0; i < 4; i++) {
        const int m = row0 + (ty << 2) + i;
        const int bb = m >> 11;
        const int ss = m & (SEQ - 1);
#pragma unroll
        for (int j = 0; j < 4; j++) {
            const int n = col0 + (tx << 2) + j;
            const float v = acc[i][j] + bias[n];
            if (cHead) {
                const int hh = n >> 6;
                const int dd = n & (HDIM - 1);
                C[(((size_t)bb * HEADS + hh) * SEQ + ss) * HDIM + dd] = v;
            } else {
                C[(size_t)m * DMODEL + n] = v;
            }
        }
    }
}

// ---------------------------------------------------------------------------
// Flash attention: grid (S/128, H, B), 128 threads. Thread t owns query row
// blockIdx.x*128+t. K/V staged in smem in 32-row tiles; all smem reads in the
// score/AV loops are identical across the warp -> broadcast (conflict-free).
// ---------------------------------------------------------------------------
__global__ __launch_bounds__(128, 1) void attn_kernel()
{
    const int TK = 32;
    __shared__ float sK[TK * HDIM];
    __shared__ float sV[TK * HDIM];

    const int tid = threadIdx.x;
    const int h = blockIdx.y;
    const int b = blockIdx.z;
    const size_t base = (((size_t)b * HEADS + h) * SEQ) * HDIM;
    const int row = blockIdx.x * 128 + tid;

    // q row, pre-scaled by 1/sqrt(hd)
    float q[HDIM];
    {
        const float* qp = g_Q + base + (size_t)row * HDIM;
#pragma unroll
        for (int d4 = 0; d4 < HDIM / 4; d4++) {
            const float4 v = *reinterpret_cast<const float4*>(qp + d4 * 4);
            q[4 * d4 + 0] = v.x * 0.125f;
            q[4 * d4 + 1] = v.y * 0.125f;
            q[4 * d4 + 2] = v.z * 0.125f;
            q[4 * d4 + 3] = v.w * 0.125f;
        }
    }

    float acc[HDIM];
#pragma unroll
    for (int d = 0; d < HDIM; d++) acc[d] = 0.0f;
    float mrun = -1e30f;
    float lrun = 0.0f;

    for (int kt = 0; kt < SEQ / TK; kt++) {
        // cooperative tile load: 32x64 floats = 512 float4 per tile
#pragma unroll
        for (int it = 0; it < 4; it++) {
            const int f = tid + 128 * it;       // 0..511
            const int r = f >> 4;               // 0..31
            const int c = (f & 15) << 2;        // 0..60
            const size_t src = base + (size_t)(kt * TK + r) * HDIM + c;
            *reinterpret_cast<float4*>(&sK[r * HDIM + c]) =
                *reinterpret_cast<const float4*>(g_K + src);
            *reinterpret_cast<float4*>(&sV[r * HDIM + c]) =
                *reinterpret_cast<const float4*>(g_V + src);
        }
        __syncthreads();

        // scores for this tile
        float s[TK];
#pragma unroll
        for (int j = 0; j < TK; j++) {
            float sum = 0.0f;
#pragma unroll
            for (int d4 = 0; d4 < HDIM / 4; d4++) {
                const float4 kv = *reinterpret_cast<const float4*>(&sK[j * HDIM + d4 * 4]);
                sum += q[4 * d4 + 0] * kv.x;
                sum += q[4 * d4 + 1] * kv.y;
                sum += q[4 * d4 + 2] * kv.z;
                sum += q[4 * d4 + 3] * kv.w;
            }
            s[j] = sum;
        }

        // online softmax update
        float mnew = mrun;
#pragma unroll
        for (int j = 0; j < TK; j++) mnew = fmaxf(mnew, s[j]);
        const float corr = __expf(mrun - mnew);
        float psum = 0.0f;
#pragma unroll
        for (int j = 0; j < TK; j++) {
            s[j] = __expf(s[j] - mnew);
            psum += s[j];
        }
        lrun = lrun * corr + psum;
        mrun = mnew;
#pragma unroll
        for (int d = 0; d < HDIM; d++) acc[d] *= corr;

        // acc += P @ V
#pragma unroll
        for (int j = 0; j < TK; j++) {
            const float p = s[j];
#pragma unroll
            for (int d4 = 0; d4 < HDIM / 4; d4++) {
                const float4 vv = *reinterpret_cast<const float4*>(&sV[j * HDIM + d4 * 4]);
                acc[4 * d4 + 0] += p * vv.x;
                acc[4 * d4 + 1] += p * vv.y;
                acc[4 * d4 + 2] += p * vv.z;
                acc[4 * d4 + 3] += p * vv.w;
            }
        }
        __syncthreads();
    }

    const float inv = 1.0f / lrun;
    float* op = g_O + base + (size_t)row * HDIM;
#pragma unroll
    for (int d4 = 0; d4 < HDIM / 4; d4++) {
        float4 v;
        v.x = acc[4 * d4 + 0] * inv;
        v.y = acc[4 * d4 + 1] * inv;
        v.z = acc[4 * d4 + 2] * inv;
        v.w = acc[4 * d4 + 3] * inv;
        *reinterpret_cast<float4*>(op + d4 * 4) = v;
    }
}

// ---------------------------------------------------------------------------
extern "C" void kernel_launch(void* const* d_in, const int* in_sizes, int n_in,
                              void* d_out, int out_size)
{
    const float* query = (const float*)d_in[0];
    const float* key   = (const float*)d_in[1];
    const float* value = (const float*)d_in[2];
    const float* Wq    = (const float*)d_in[3];
    const float* bq    = (const float*)d_in[4];
    const float* Wk    = (const float*)d_in[5];
    const float* bk    = (const float*)d_in[6];
    const float* Wv    = (const float*)d_in[7];
    const float* bv    = (const float*)d_in[8];
    const float* Wo    = (const float*)d_in[9];
    const float* bo    = (const float*)d_in[10];
    float* out = (float*)d_out;

    float *pQ, *pK, *pV, *pO;
    cudaGetSymbolAddress((void**)&pQ, g_Q);
    cudaGetSymbolAddress((void**)&pK, g_K);
    cudaGetSymbolAddress((void**)&pV, g_V);
    cudaGetSymbolAddress((void**)&pO, g_O);

    const dim3 gblk(16, 16);                       // 256 threads
    const dim3 ggrid(DMODEL / 64, MTOT / 64);      // 16 x 64

    // QKV projections -> head-layout scratch
    gemm_proj<<<ggrid, gblk>>>(query, Wq, bq, pQ, 0, 1);
    gemm_proj<<<ggrid, gblk>>>(key,   Wk, bk, pK, 0, 1);
    gemm_proj<<<ggrid, gblk>>>(value, Wv, bv, pV, 0, 1);

    // attention
    const dim3 agrid(SEQ / 128, HEADS, BATCH);
    attn_kernel<<<agrid, 128>>>();

    // output projection: head-layout A -> contiguous out
    gemm_proj<<<ggrid, gblk>>>(pO, Wo, bo, out, 1, 0);
}

// round 4
// speedup vs baseline: 2.3222x; 2.3222x over previous
#include <cuda_runtime.h>
#include <cuda_bf16.h>
#include <cstdint>
#include <math.h>

// Problem constants: B=2, S=2048, D=1024, H=16, hd=64
#define BATCH  2
#define SEQ    2048
#define DMODEL 1024
#define HEADS  16
#define HDIM   64
#define MTOT   (BATCH * SEQ)        // 4096
#define KSPLIT (3 * DMODEL)         // 3072 : [hi|hi|lo] x [hi|lo|hi] split GEMM

// ---------------- device scratch (no allocations allowed) -------------------
__device__ float g_Q[BATCH * HEADS * SEQ * HDIM];
__device__ float g_K[BATCH * HEADS * SEQ * HDIM];
__device__ float g_V[BATCH * HEADS * SEQ * HDIM];
__device__ float g_O[BATCH * HEADS * SEQ * HDIM];
__device__ __nv_bfloat16 g_Abig[(size_t)MTOT * KSPLIT];     // 25 MB
__device__ __nv_bfloat16 g_Wbig[(size_t)DMODEL * KSPLIT];   // 6 MB

// ---------------- helpers ----------------------------------------------------
__device__ __forceinline__ uint32_t smem_u32(const void* p) {
    uint32_t a;
    asm("{ .reg .u64 t; cvta.to.shared.u64 t, %1; cvt.u32.u64 %0, t; }"
        : "=r"(a) : "l"(p));
    return a;
}
#define CP_ASYNC16(dst, src) \
    asm volatile("cp.async.cg.shared.global [%0], [%1], 16;" :: "r"(dst), "l"(src))
#define CP_COMMIT() asm volatile("cp.async.commit_group;" ::: "memory")
#define CP_WAIT(n)  asm volatile("cp.async.wait_group %0;" :: "n"(n) : "memory")

__device__ __forceinline__ void ldmatrix_x4(uint32_t* r, uint32_t addr) {
    asm volatile("ldmatrix.sync.aligned.m8n8.x4.shared.b16 {%0,%1,%2,%3}, [%4];"
                 : "=r"(r[0]), "=r"(r[1]), "=r"(r[2]), "=r"(r[3]) : "r"(addr));
}
__device__ __forceinline__ void mma_bf16(float* c, const uint32_t* a,
                                         uint32_t b0, uint32_t b1) {
    asm volatile(
        "mma.sync.aligned.m16n8k16.row.col.f32.bf16.bf16.f32 "
        "{%0,%1,%2,%3}, {%4,%5,%6,%7}, {%8,%9}, {%0,%1,%2,%3};"
        : "+f"(c[0]), "+f"(c[1]), "+f"(c[2]), "+f"(c[3])
        : "r"(a[0]), "r"(a[1]), "r"(a[2]), "r"(a[3]), "r"(b0), "r"(b1));
}

// ---------------------------------------------------------------------------
// Split kernel: X fp32 -> Y bf16 [rows, 3072]; seg `loSeg` holds the bf16
// residual lo(x), the other two segments hold hi(x).
// srcHead: X is [B,H,S,hd]; else [rows, 1024] row-major.
// ---------------------------------------------------------------------------
__global__ __launch_bounds__(256) void split_kernel(
    const float* __restrict__ X, __nv_bfloat16* __restrict__ Y,
    int srcHead, int loSeg)
{
    const int idx = blockIdx.x * 256 + threadIdx.x;   // one per 4 floats
    const int m = idx >> 8;
    const int k = (idx & 255) << 2;

    const float* src;
    if (srcHead) {
        const int bb = m >> 11, ss = m & (SEQ - 1);
        const int hh = k >> 6, dd = k & (HDIM - 1);
        src = X + ((((size_t)bb * HEADS + hh) * SEQ + ss) * HDIM + dd);
    } else {
        src = X + (size_t)m * DMODEL + k;
    }
    const float4 v = *reinterpret_cast<const float4*>(src);

    union Pack { __nv_bfloat16 b[4]; uint2 u; };
    Pack hi, lo;
    hi.b[0] = __float2bfloat16(v.x); lo.b[0] = __float2bfloat16(v.x - __bfloat162float(hi.b[0]));
    hi.b[1] = __float2bfloat16(v.y); lo.b[1] = __float2bfloat16(v.y - __bfloat162float(hi.b[1]));
    hi.b[2] = __float2bfloat16(v.z); lo.b[2] = __float2bfloat16(v.z - __bfloat162float(hi.b[2]));
    hi.b[3] = __float2bfloat16(v.w); lo.b[3] = __float2bfloat16(v.w - __bfloat162float(hi.b[3]));

    __nv_bfloat16* yrow = Y + (size_t)m * KSPLIT + k;
#pragma unroll
    for (int seg = 0; seg < 3; seg++) {
        *reinterpret_cast<uint2*>(yrow + seg * DMODEL) = (seg == loSeg) ? lo.u : hi.u;
    }
}

// ---------------------------------------------------------------------------
// HMMA bf16 GEMM: C[m,n] = sum_k A[m,k]*B[n,k] + bias[n]
// A: [4096, 3072] bf16, B: [1024, 3072] bf16 (K-major).
// CTA tile 128x128, 256 threads (8 warps, 2(M) x 4(N), warp tile 64x32).
// K chunked by 64, cp.async double-buffered, ldmatrix from swizzled smem.
// cHead: C written to [B,H,S,hd]; else [m, 1024] row-major.
// ---------------------------------------------------------------------------
__global__ __launch_bounds__(256, 1)
void gemm_hmma(const __nv_bfloat16* __restrict__ A, const __nv_bfloat16* __restrict__ B,
               const float* __restrict__ bias, float* __restrict__ C, int cHead)
{
    // row = 128 bytes (64 bf16); 16B group g stored at g ^ (row & 7)
    __shared__ __align__(128) __nv_bfloat16 sA[2][128 * 64];   // 2 x 16 KB
    __shared__ __align__(128) __nv_bfloat16 sB[2][128 * 64];

    const int tid = threadIdx.x;
    const int wid = tid >> 5;
    const int l   = tid & 31;
    const int wm  = wid & 1;          // 0..1  (M)
    const int wn  = wid >> 1;         // 0..3  (N)
    const int row0 = blockIdx.y * 128;
    const int col0 = blockIdx.x * 128;

    const uint32_t aBase[2] = { smem_u32(sA[0]), smem_u32(sA[1]) };
    const uint32_t bBase[2] = { smem_u32(sB[0]), smem_u32(sB[1]) };

    float acc[4][4][4];
#pragma unroll
    for (int i = 0; i < 4; i++)
#pragma unroll
        for (int j = 0; j < 4; j++)
#pragma unroll
            for (int c = 0; c < 4; c++) acc[i][j][c] = 0.0f;

    // ldmatrix per-lane addressing pieces
    const int lr15 = l & 15;          // row within 16-row tile
    const int lkh  = (l >> 4) & 1;    // k-half select

    const int NCHUNK = KSPLIT / 64;   // 48

    // ---- async tile loader: 1024 16B chunks per (A,B) pair, 4 per thread each
    auto load_tiles = [&](int i, int buf) {
        const int k0 = i * 64;
#pragma unroll
        for (int it = 0; it < 4; it++) {
            const int idx = it * 256 + tid;        // 0..1023
            const int r = idx >> 3;
            const int g = idx & 7;
            const uint32_t off = (uint32_t)(r * 128 + ((g ^ (r & 7)) << 4));
            CP_ASYNC16(aBase[buf] + off,
                       A + (size_t)(row0 + r) * KSPLIT + k0 + g * 8);
            CP_ASYNC16(bBase[buf] + off,
                       B + (size_t)(col0 + r) * KSPLIT + k0 + g * 8);
        }
    };

    load_tiles(0, 0);
    CP_COMMIT();

    for (int i = 0; i < NCHUNK; i++) {
        const int buf = i & 1;
        if (i + 1 < NCHUNK) {
            load_tiles(i + 1, buf ^ 1);
            CP_COMMIT();
            CP_WAIT(1);
        } else {
            CP_WAIT(0);
        }
        __syncthreads();

#pragma unroll
        for (int ks = 0; ks < 4; ks++) {          // k16 steps within BK=64
            // A fragments: 4 m16 tiles
            uint32_t afr[4][4];
#pragma unroll
            for (int mt = 0; mt < 4; mt++) {
                const int r = wm * 64 + mt * 16 + lr15;
                const int g = ks * 2 + lkh;
                ldmatrix_x4(afr[mt],
                            aBase[buf] + r * 128 + (((g ^ (r & 7))) << 4));
            }
            // B fragments: 2 x (n16 x k16) tiles covering n=32
            uint32_t bfr[2][4];
#pragma unroll
            for (int hb = 0; hb < 2; hb++) {
                const int r = wn * 32 + hb * 16 + lr15;
                const int g = ks * 2 + lkh;
                ldmatrix_x4(bfr[hb],
                            bBase[buf] + r * 128 + (((g ^ (r & 7))) << 4));
            }
#pragma unroll
            for (int mt = 0; mt < 4; mt++)
#pragma unroll
                for (int nt = 0; nt < 4; nt++)
                    mma_bf16(acc[mt][nt], afr[mt],
                             bfr[nt >> 1][nt & 1], bfr[nt >> 1][2 + (nt & 1)]);
        }
        __syncthreads();
    }

    // ---- epilogue: bias + store ----
#pragma unroll
    for (int mt = 0; mt < 4; mt++) {
#pragma unroll
        for (int nt = 0; nt < 4; nt++) {
            const int n = col0 + wn * 32 + nt * 8 + 2 * (l & 3);
            const float2 bv = *reinterpret_cast<const float2*>(bias + n);
#pragma unroll
            for (int half = 0; half < 2; half++) {
                const int m = row0 + wm * 64 + mt * 16 + (l >> 2) + half * 8;
                float2 v;
                v.x = acc[mt][nt][2 * half + 0] + bv.x;
                v.y = acc[mt][nt][2 * half + 1] + bv.y;
                if (cHead) {
                    const int bb = m >> 11, ss = m & (SEQ - 1);
                    const int hh = n >> 6, dd = n & (HDIM - 1);
                    *reinterpret_cast<float2*>(
                        C + (((size_t)bb * HEADS + hh) * SEQ + ss) * HDIM + dd) = v;
                } else {
                    *reinterpret_cast<float2*>(C + (size_t)m * DMODEL + n) = v;
                }
            }
        }
    }
}

// ---------------------------------------------------------------------------
// Flash attention (fp32 SIMT, unchanged): 1 thread = 1 query row.
// ---------------------------------------------------------------------------
__global__ __launch_bounds__(128, 1) void attn_kernel()
{
    const int TK = 32;
    __shared__ float sK[TK * HDIM];
    __shared__ float sV[TK * HDIM];

    const int tid = threadIdx.x;
    const int h = blockIdx.y;
    const int b = blockIdx.z;
    const size_t base = (((size_t)b * HEADS + h) * SEQ) * HDIM;
    const int row = blockIdx.x * 128 + tid;

    float q[HDIM];
    {
        const float* qp = g_Q + base + (size_t)row * HDIM;
#pragma unroll
        for (int d4 = 0; d4 < HDIM / 4; d4++) {
            const float4 v = *reinterpret_cast<const float4*>(qp + d4 * 4);
            q[4 * d4 + 0] = v.x * 0.125f;
            q[4 * d4 + 1] = v.y * 0.125f;
            q[4 * d4 + 2] = v.z * 0.125f;
            q[4 * d4 + 3] = v.w * 0.125f;
        }
    }

    float acc[HDIM];
#pragma unroll
    for (int d = 0; d < HDIM; d++) acc[d] = 0.0f;
    float mrun = -1e30f;
    float lrun = 0.0f;

    for (int kt = 0; kt < SEQ / TK; kt++) {
#pragma unroll
        for (int it = 0; it < 4; it++) {
            const int f = tid + 128 * it;
            const int r = f >> 4;
            const int c = (f & 15) << 2;
            const size_t src = base + (size_t)(kt * TK + r) * HDIM + c;
            *reinterpret_cast<float4*>(&sK[r * HDIM + c]) =
                *reinterpret_cast<const float4*>(g_K + src);
            *reinterpret_cast<float4*>(&sV[r * HDIM + c]) =
                *reinterpret_cast<const float4*>(g_V + src);
        }
        __syncthreads();

        float s[TK];
#pragma unroll
        for (int j = 0; j < TK; j++) {
            float sum = 0.0f;
#pragma unroll
            for (int d4 = 0; d4 < HDIM / 4; d4++) {
                const float4 kv = *reinterpret_cast<const float4*>(&sK[j * HDIM + d4 * 4]);
                sum += q[4 * d4 + 0] * kv.x;
                sum += q[4 * d4 + 1] * kv.y;
                sum += q[4 * d4 + 2] * kv.z;
                sum += q[4 * d4 + 3] * kv.w;
            }
            s[j] = sum;
        }

        float mnew = mrun;
#pragma unroll
        for (int j = 0; j < TK; j++) mnew = fmaxf(mnew, s[j]);
        const float corr = __expf(mrun - mnew);
        float psum = 0.0f;
#pragma unroll
        for (int j = 0; j < TK; j++) {
            s[j] = __expf(s[j] - mnew);
            psum += s[j];
        }
        lrun = lrun * corr + psum;
        mrun = mnew;
#pragma unroll
        for (int d = 0; d < HDIM; d++) acc[d] *= corr;

#pragma unroll
        for (int j = 0; j < TK; j++) {
            const float p = s[j];
#pragma unroll
            for (int d4 = 0; d4 < HDIM / 4; d4++) {
                const float4 vv = *reinterpret_cast<const float4*>(&sV[j * HDIM + d4 * 4]);
                acc[4 * d4 + 0] += p * vv.x;
                acc[4 * d4 + 1] += p * vv.y;
                acc[4 * d4 + 2] += p * vv.z;
                acc[4 * d4 + 3] += p * vv.w;
            }
        }
        __syncthreads();
    }

    const float inv = 1.0f / lrun;
    float* op = g_O + base + (size_t)row * HDIM;
#pragma unroll
    for (int d4 = 0; d4 < HDIM / 4; d4++) {
        float4 v;
        v.x = acc[4 * d4 + 0] * inv;
        v.y = acc[4 * d4 + 1] * inv;
        v.z = acc[4 * d4 + 2] * inv;
        v.w = acc[4 * d4 + 3] * inv;
        *reinterpret_cast<float4*>(op + d4 * 4) = v;
    }
}

// ---------------------------------------------------------------------------
extern "C" void kernel_launch(void* const* d_in, const int* in_sizes, int n_in,
                              void* d_out, int out_size)
{
    const float* query = (const float*)d_in[0];
    const float* key   = (const float*)d_in[1];
    const float* value = (const float*)d_in[2];
    const float* Wq    = (const float*)d_in[3];
    const float* bq    = (const float*)d_in[4];
    const float* Wk    = (const float*)d_in[5];
    const float* bk    = (const float*)d_in[6];
    const float* Wv    = (const float*)d_in[7];
    const float* bv    = (const float*)d_in[8];
    const float* Wo    = (const float*)d_in[9];
    const float* bo    = (const float*)d_in[10];
    float* out = (float*)d_out;

    float *pQ, *pK, *pV, *pO;
    __nv_bfloat16 *pA, *pW;
    cudaGetSymbolAddress((void**)&pQ, g_Q);
    cudaGetSymbolAddress((void**)&pK, g_K);
    cudaGetSymbolAddress((void**)&pV, g_V);
    cudaGetSymbolAddress((void**)&pO, g_O);
    cudaGetSymbolAddress((void**)&pA, g_Abig);
    cudaGetSymbolAddress((void**)&pW, g_Wbig);

    const dim3 ggrid(DMODEL / 128, MTOT / 128);   // 8 x 32 = 256 CTAs

    // Q = query @ Wq^T + bq  -> head layout
    split_kernel<<<MTOT, 256>>>(query, pA, 0, 2);
    split_kernel<<<DMODEL, 256>>>(Wq, pW, 0, 1);
    gemm_hmma<<<ggrid, 256>>>(pA, pW, bq, pQ, 1);

    split_kernel<<<MTOT, 256>>>(key, pA, 0, 2);
    split_kernel<<<DMODEL, 256>>>(Wk, pW, 0, 1);
    gemm_hmma<<<ggrid, 256>>>(pA, pW, bk, pK, 1);

    split_kernel<<<MTOT, 256>>>(value, pA, 0, 2);
    split_kernel<<<DMODEL, 256>>>(Wv, pW, 0, 1);
    gemm_hmma<<<ggrid, 256>>>(pA, pW, bv, pV, 1);

    // attention
    const dim3 agrid(SEQ / 128, HEADS, BATCH);
    attn_kernel<<<agrid, 128>>>();

    // out = O @ Wo^T + bo  (O is head layout)
    split_kernel<<<MTOT, 256>>>(pO, pA, 1, 2);
    split_kernel<<<DMODEL, 256>>>(Wo, pW, 0, 1);
    gemm_hmma<<<ggrid, 256>>>(pA, pW, bo, out, 0);
}

// round 6
// speedup vs baseline: 5.2667x; 2.2680x over previous
#include <cuda_runtime.h>
#include <cuda_bf16.h>
#include <cstdint>
#include <math.h>

// Problem constants: B=2, S=2048, D=1024, H=16, hd=64
#define BATCH  2
#define SEQ    2048
#define DMODEL 1024
#define HEADS  16
#define HDIM   64
#define MTOT   (BATCH * SEQ)        // 4096
#define KSPLIT (3 * DMODEL)         // 3072 : [hi|hi|lo] x [hi|lo|hi] split GEMM

#define QSCALE 0.18033688011112042f   // 0.125 * log2(e): softmax in exp2 domain

// ---------------- device scratch (no allocations allowed) -------------------
__device__ __nv_bfloat16 g_Abig[(size_t)MTOT * KSPLIT];     // 25 MB
__device__ __nv_bfloat16 g_Wbig[(size_t)DMODEL * KSPLIT];   // 6 MB
__device__ __nv_bfloat16 g_Qh[BATCH * HEADS * SEQ * HDIM];  // head layout [B,H,S,hd]
__device__ __nv_bfloat16 g_Ql[BATCH * HEADS * SEQ * HDIM];
__device__ __nv_bfloat16 g_Kh[BATCH * HEADS * SEQ * HDIM];
__device__ __nv_bfloat16 g_Kl[BATCH * HEADS * SEQ * HDIM];
__device__ __nv_bfloat16 g_Vh[BATCH * HEADS * SEQ * HDIM];
__device__ __nv_bfloat16 g_Vl[BATCH * HEADS * SEQ * HDIM];

// ---------------- helpers ----------------------------------------------------
__device__ __forceinline__ uint32_t smem_u32(const void* p) {
    uint32_t a;
    asm("{ .reg .u64 t; cvta.to.shared.u64 t, %1; cvt.u32.u64 %0, t; }"
        : "=r"(a) : "l"(p));
    return a;
}
#define CP_ASYNC16(dst, src) \
    asm volatile("cp.async.cg.shared.global [%0], [%1], 16;" :: "r"(dst), "l"(src))
#define CP_COMMIT() asm volatile("cp.async.commit_group;" ::: "memory")
#define CP_WAIT(n)  asm volatile("cp.async.wait_group %0;" :: "n"(n) : "memory")

__device__ __forceinline__ void ldmatrix_x4(uint32_t* r, uint32_t addr) {
    asm volatile("ldmatrix.sync.aligned.m8n8.x4.shared.b16 {%0,%1,%2,%3}, [%4];"
                 : "=r"(r[0]), "=r"(r[1]), "=r"(r[2]), "=r"(r[3]) : "r"(addr));
}
__device__ __forceinline__ void ldmatrix_x4_trans(uint32_t* r, uint32_t addr) {
    asm volatile("ldmatrix.sync.aligned.m8n8.x4.trans.shared.b16 {%0,%1,%2,%3}, [%4];"
                 : "=r"(r[0]), "=r"(r[1]), "=r"(r[2]), "=r"(r[3]) : "r"(addr));
}
__device__ __forceinline__ void mma_bf16(float* c, const uint32_t* a,
                                         uint32_t b0, uint32_t b1) {
    asm volatile(
        "mma.sync.aligned.m16n8k16.row.col.f32.bf16.bf16.f32 "
        "{%0,%1,%2,%3}, {%4,%5,%6,%7}, {%8,%9}, {%0,%1,%2,%3};"
        : "+f"(c[0]), "+f"(c[1]), "+f"(c[2]), "+f"(c[3])
        : "r"(a[0]), "r"(a[1]), "r"(a[2]), "r"(a[3]), "r"(b0), "r"(b1));
}
__device__ __forceinline__ uint32_t pack_bf16x2(float hi, float lo) {
    uint32_t d;
    asm("cvt.rn.bf16x2.f32 %0, %1, %2;" : "=r"(d) : "f"(hi), "f"(lo));
    return d;
}
__device__ __forceinline__ float ex2f(float x) {
    float r;
    asm("ex2.approx.f32 %0, %1;" : "=f"(r) : "f"(x));
    return r;
}
__device__ __forceinline__ float bf16_round(float x) {
    return __bfloat162float(__float2bfloat16(x));
}

// ---------------------------------------------------------------------------
// Split kernel: X fp32 [rows,1024] -> Y bf16 [rows, 3072]; seg `loSeg` holds
// the bf16 residual lo(x), the other two segments hold hi(x).
// ---------------------------------------------------------------------------
__global__ __launch_bounds__(256) void split_kernel(
    const float* __restrict__ X, __nv_bfloat16* __restrict__ Y, int loSeg)
{
    const int idx = blockIdx.x * 256 + threadIdx.x;   // one per 4 floats
    const int m = idx >> 8;
    const int k = (idx & 255) << 2;

    const float4 v = *reinterpret_cast<const float4*>(X + (size_t)m * DMODEL + k);

    union Pack { __nv_bfloat16 b[4]; uint2 u; };
    Pack hi, lo;
    hi.b[0] = __float2bfloat16(v.x); lo.b[0] = __float2bfloat16(v.x - __bfloat162float(hi.b[0]));
    hi.b[1] = __float2bfloat16(v.y); lo.b[1] = __float2bfloat16(v.y - __bfloat162float(hi.b[1]));
    hi.b[2] = __float2bfloat16(v.z); lo.b[2] = __float2bfloat16(v.z - __bfloat162float(hi.b[2]));
    hi.b[3] = __float2bfloat16(v.w); lo.b[3] = __float2bfloat16(v.w - __bfloat162float(hi.b[3]));

    __nv_bfloat16* yrow = Y + (size_t)m * KSPLIT + k;
#pragma unroll
    for (int seg = 0; seg < 3; seg++) {
        *reinterpret_cast<uint2*>(yrow + seg * DMODEL) = (seg == loSeg) ? lo.u : hi.u;
    }
}

// ---------------------------------------------------------------------------
// HMMA bf16 GEMM: C[m,n] = (sum_k A[m,k]*B[n,k] + bias[n]) * scale
// mode 0: C fp32 row-major [m, 1024]
// mode 1: bf16 hi/lo split written to Ch/Cl in head layout [B,H,S,hd]
// ---------------------------------------------------------------------------
__global__ __launch_bounds__(256, 1)
void gemm_hmma(const __nv_bfloat16* __restrict__ A, const __nv_bfloat16* __restrict__ B,
               const float* __restrict__ bias, float* __restrict__ C,
               __nv_bfloat16* __restrict__ Ch, __nv_bfloat16* __restrict__ Cl,
               float scale, int mode)
{
    __shared__ __align__(128) __nv_bfloat16 sA[2][128 * 64];   // 2 x 16 KB
    __shared__ __align__(128) __nv_bfloat16 sB[2][128 * 64];

    const int tid = threadIdx.x;
    const int wid = tid >> 5;
    const int l   = tid & 31;
    const int wm  = wid & 1;
    const int wn  = wid >> 1;
    const int row0 = blockIdx.y * 128;
    const int col0 = blockIdx.x * 128;

    const uint32_t aBase[2] = { smem_u32(sA[0]), smem_u32(sA[1]) };
    const uint32_t bBase[2] = { smem_u32(sB[0]), smem_u32(sB[1]) };

    float acc[4][4][4];
#pragma unroll
    for (int i = 0; i < 4; i++)
#pragma unroll
        for (int j = 0; j < 4; j++)
#pragma unroll
            for (int c = 0; c < 4; c++) acc[i][j][c] = 0.0f;

    const int lr15 = l & 15;
    const int lkh  = (l >> 4) & 1;
    const int NCHUNK = KSPLIT / 64;   // 48

    auto load_tiles = [&](int i, int buf) {
        const int k0 = i * 64;
#pragma unroll
        for (int it = 0; it < 4; it++) {
            const int idx = it * 256 + tid;
            const int r = idx >> 3;
            const int g = idx & 7;
            const uint32_t off = (uint32_t)(r * 128 + ((g ^ (r & 7)) << 4));
            CP_ASYNC16(aBase[buf] + off, A + (size_t)(row0 + r) * KSPLIT + k0 + g * 8);
            CP_ASYNC16(bBase[buf] + off, B + (size_t)(col0 + r) * KSPLIT + k0 + g * 8);
        }
    };

    load_tiles(0, 0);
    CP_COMMIT();

    for (int i = 0; i < NCHUNK; i++) {
        const int buf = i & 1;
        if (i + 1 < NCHUNK) {
            load_tiles(i + 1, buf ^ 1);
            CP_COMMIT();
            CP_WAIT(1);
        } else {
            CP_WAIT(0);
        }
        __syncthreads();

#pragma unroll
        for (int ks = 0; ks < 4; ks++) {
            uint32_t afr[4][4];
#pragma unroll
            for (int mt = 0; mt < 4; mt++) {
                const int r = wm * 64 + mt * 16 + lr15;
                const int g = ks * 2 + lkh;
                ldmatrix_x4(afr[mt], aBase[buf] + r * 128 + ((g ^ (r & 7)) << 4));
            }
            uint32_t bfr[2][4];
#pragma unroll
            for (int hb = 0; hb < 2; hb++) {
                const int r = wn * 32 + hb * 16 + lr15;
                const int g = ks * 2 + lkh;
                ldmatrix_x4(bfr[hb], bBase[buf] + r * 128 + ((g ^ (r & 7)) << 4));
            }
#pragma unroll
            for (int mt = 0; mt < 4; mt++)
#pragma unroll
                for (int nt = 0; nt < 4; nt++)
                    mma_bf16(acc[mt][nt], afr[mt],
                             bfr[nt >> 1][nt & 1], bfr[nt >> 1][2 + (nt & 1)]);
        }
        __syncthreads();
    }

    // ---- epilogue ----
#pragma unroll
    for (int mt = 0; mt < 4; mt++) {
#pragma unroll
        for (int nt = 0; nt < 4; nt++) {
            const int n = col0 + wn * 32 + nt * 8 + 2 * (l & 3);
            const float2 bv = *reinterpret_cast<const float2*>(bias + n);
#pragma unroll
            for (int half = 0; half < 2; half++) {
                const int m = row0 + wm * 64 + mt * 16 + (l >> 2) + half * 8;
                const float vx = (acc[mt][nt][2 * half + 0] + bv.x) * scale;
                const float vy = (acc[mt][nt][2 * half + 1] + bv.y) * scale;
                if (mode == 0) {
                    float2 v; v.x = vx; v.y = vy;
                    *reinterpret_cast<float2*>(C + (size_t)m * DMODEL + n) = v;
                } else {
                    const int bb = m >> 11, ss = m & (SEQ - 1);
                    const int hh = n >> 6, dd = n & (HDIM - 1);
                    const size_t off = (((size_t)bb * HEADS + hh) * SEQ + ss) * HDIM + dd;
                    const uint32_t hi = pack_bf16x2(vy, vx);
                    const uint32_t lo = pack_bf16x2(vy - bf16_round(vy), vx - bf16_round(vx));
                    *reinterpret_cast<uint32_t*>(Ch + off) = hi;
                    *reinterpret_cast<uint32_t*>(Cl + off) = lo;
                }
            }
        }
    }
}

// ---------------------------------------------------------------------------
// Tensor-core flash attention, split-bf16 compensated.
// Grid (S/128, H, B), 256 threads (8 warps x 16 q-rows). Bc = 64.
// Scores are in exp2 domain (Q pre-scaled by 0.125*log2e at projection).
// Output written as bf16 hi/hi/lo directly into g_Abig for the final GEMM.
// Dynamic smem: Qh(16K) Ql(16K) + 2 stages x [Kh Kl Vh Vl](8K each) = 96 KB.
// ---------------------------------------------------------------------------
__global__ __launch_bounds__(256, 1) void attn_tc()
{
    extern __shared__ __align__(128) char smem[];
    const uint32_t sQH  = smem_u32(smem);
    const uint32_t sQL  = sQH + 16384;
    const uint32_t sKV0 = sQL + 16384;     // stage s at sKV0 + s*32768

    const int tid = threadIdx.x;
    const int wid = tid >> 5;
    const int l   = tid & 31;
    const int h = blockIdx.y;
    const int b = blockIdx.z;
    const int q0 = blockIdx.x * 128;
    const size_t base = (((size_t)b * HEADS + h) * SEQ) * HDIM;

    // ---- async Q load (both hi and lo) ----
#pragma unroll
    for (int it = 0; it < 8; it++) {
        const int half = it >> 2;
        const int rem = (it & 3) * 256 + tid;      // 0..1023
        const int r = rem >> 3;
        const int g = tid & 7;
        const __nv_bfloat16* src = (half ? g_Ql : g_Qh) + base + (size_t)(q0 + r) * HDIM + g * 8;
        CP_ASYNC16((half ? sQL : sQH) + r * 128 + ((g ^ (r & 7)) << 4), src);
    }

    auto load_kv = [&](int kt, int stage) {
        const int kv0 = kt * 64;
        const uint32_t sb = sKV0 + stage * 32768;
#pragma unroll
        for (int it = 0; it < 8; it++) {
            const int tile = it >> 1;                 // Kh, Kl, Vh, Vl
            const int rem = (it & 1) * 256 + tid;     // 0..511
            const int r = rem >> 3;
            const int g = tid & 7;
            const __nv_bfloat16* tp =
                (tile == 0) ? g_Kh : (tile == 1) ? g_Kl : (tile == 2) ? g_Vh : g_Vl;
            CP_ASYNC16(sb + tile * 8192 + r * 128 + ((g ^ (r & 7)) << 4),
                       tp + base + (size_t)(kv0 + r) * HDIM + g * 8);
        }
    };

    load_kv(0, 0);
    CP_COMMIT();

    float oacc[8][4];
#pragma unroll
    for (int i = 0; i < 8; i++)
#pragma unroll
        for (int c = 0; c < 4; c++) oacc[i][c] = 0.0f;
    float mrow0 = -1e30f, mrow1 = -1e30f;
    float lrow0 = 0.0f, lrow1 = 0.0f;

    uint32_t aH[4][4], aL[4][4];

    const int NT = SEQ / 64;   // 32
    for (int kt = 0; kt < NT; kt++) {
        const int buf = kt & 1;
        if (kt + 1 < NT) {
            load_kv(kt + 1, buf ^ 1);
            CP_COMMIT();
            CP_WAIT(1);
        } else {
            CP_WAIT(0);
        }
        __syncthreads();

        if (kt == 0) {
            // Q fragments (once; Q smem arrived with group 0)
#pragma unroll
            for (int ks = 0; ks < 4; ks++) {
                const int r = wid * 16 + (l & 15);
                const int g = ks * 2 + (l >> 4);
                const uint32_t off = r * 128 + ((g ^ (r & 7)) << 4);
                ldmatrix_x4(aH[ks], sQH + off);
                ldmatrix_x4(aL[ks], sQL + off);
            }
        }

        const uint32_t sKH = sKV0 + buf * 32768;
        const uint32_t sKL = sKH + 8192;
        const uint32_t sVH = sKH + 16384;
        const uint32_t sVL = sKH + 24576;

        // ---- S = Qh*Kh + Qh*Kl + Ql*Kh  (16 x 64 per warp) ----
        float sacc[8][4];
#pragma unroll
        for (int i = 0; i < 8; i++)
#pragma unroll
            for (int c = 0; c < 4; c++) sacc[i][c] = 0.0f;

#pragma unroll
        for (int ks = 0; ks < 4; ks++) {
#pragma unroll
            for (int nb = 0; nb < 4; nb++) {
                const int r = nb * 16 + (l & 15);
                const int g = ks * 2 + (l >> 4);
                const uint32_t off = r * 128 + ((g ^ (r & 7)) << 4);
                uint32_t kh[4], kl[4];
                ldmatrix_x4(kh, sKH + off);
                ldmatrix_x4(kl, sKL + off);
                mma_bf16(sacc[2 * nb],     aH[ks], kh[0], kh[2]);
                mma_bf16(sacc[2 * nb + 1], aH[ks], kh[1], kh[3]);
                mma_bf16(sacc[2 * nb],     aH[ks], kl[0], kl[2]);
                mma_bf16(sacc[2 * nb + 1], aH[ks], kl[1], kl[3]);
                mma_bf16(sacc[2 * nb],     aL[ks], kh[0], kh[2]);
                mma_bf16(sacc[2 * nb + 1], aL[ks], kh[1], kh[3]);
            }
        }

        // ---- online softmax (exp2 domain) ----
        float mx0 = -1e30f, mx1 = -1e30f;
#pragma unroll
        for (int nt = 0; nt < 8; nt++) {
            mx0 = fmaxf(mx0, fmaxf(sacc[nt][0], sacc[nt][1]));
            mx1 = fmaxf(mx1, fmaxf(sacc[nt][2], sacc[nt][3]));
        }
        mx0 = fmaxf(mx0, __shfl_xor_sync(0xffffffffu, mx0, 1));
        mx0 = fmaxf(mx0, __shfl_xor_sync(0xffffffffu, mx0, 2));
        mx1 = fmaxf(mx1, __shfl_xor_sync(0xffffffffu, mx1, 1));
        mx1 = fmaxf(mx1, __shfl_xor_sync(0xffffffffu, mx1, 2));

        const float mn0 = fmaxf(mrow0, mx0);
        const float mn1 = fmaxf(mrow1, mx1);
        const float corr0 = ex2f(mrow0 - mn0);
        const float corr1 = ex2f(mrow1 - mn1);
        mrow0 = mn0; mrow1 = mn1;

        float ps0 = 0.0f, ps1 = 0.0f;
#pragma unroll
        for (int nt = 0; nt < 8; nt++) {
            sacc[nt][0] = ex2f(sacc[nt][0] - mn0);
            sacc[nt][1] = ex2f(sacc[nt][1] - mn0);
            sacc[nt][2] = ex2f(sacc[nt][2] - mn1);
            sacc[nt][3] = ex2f(sacc[nt][3] - mn1);
            ps0 += sacc[nt][0] + sacc[nt][1];
            ps1 += sacc[nt][2] + sacc[nt][3];
        }
        lrow0 = lrow0 * corr0 + ps0;
        lrow1 = lrow1 * corr1 + ps1;
#pragma unroll
        for (int nt = 0; nt < 8; nt++) {
            oacc[nt][0] *= corr0; oacc[nt][1] *= corr0;
            oacc[nt][2] *= corr1; oacc[nt][3] *= corr1;
        }

        // ---- O += Ph*Vh + Ph*Vl + Pl*Vh ----
#pragma unroll
        for (int ks = 0; ks < 4; ks++) {
            uint32_t pH[4], pL[4];
            {
                const float p0 = sacc[2 * ks][0],     p1 = sacc[2 * ks][1];
                const float p2 = sacc[2 * ks][2],     p3 = sacc[2 * ks][3];
                const float p4 = sacc[2 * ks + 1][0], p5 = sacc[2 * ks + 1][1];
                const float p6 = sacc[2 * ks + 1][2], p7 = sacc[2 * ks + 1][3];
                pH[0] = pack_bf16x2(p1, p0);
                pH[1] = pack_bf16x2(p3, p2);
                pH[2] = pack_bf16x2(p5, p4);
                pH[3] = pack_bf16x2(p7, p6);
                pL[0] = pack_bf16x2(p1 - bf16_round(p1), p0 - bf16_round(p0));
                pL[1] = pack_bf16x2(p3 - bf16_round(p3), p2 - bf16_round(p2));
                pL[2] = pack_bf16x2(p5 - bf16_round(p5), p4 - bf16_round(p4));
                pL[3] = pack_bf16x2(p7 - bf16_round(p7), p6 - bf16_round(p6));
            }
#pragma unroll
            for (int nb = 0; nb < 4; nb++) {
                const int r = ks * 16 + (l & 15);
                const int g = nb * 2 + (l >> 4);
                const uint32_t off = r * 128 + ((g ^ (r & 7)) << 4);
                uint32_t vh[4], vl[4];
                ldmatrix_x4_trans(vh, sVH + off);
                ldmatrix_x4_trans(vl, sVL + off);
                mma_bf16(oacc[2 * nb],     pH, vh[0], vh[1]);
                mma_bf16(oacc[2 * nb + 1], pH, vh[2], vh[3]);
                mma_bf16(oacc[2 * nb],     pH, vl[0], vl[1]);
                mma_bf16(oacc[2 * nb + 1], pH, vl[2], vl[3]);
                mma_bf16(oacc[2 * nb],     pL, vh[0], vh[1]);
                mma_bf16(oacc[2 * nb + 1], pL, vh[2], vh[3]);
            }
        }
        __syncthreads();   // all warps done with buf before it is reloaded
    }

    // ---- finalize: normalize, split to bf16 hi/lo, write into g_Abig ----
    lrow0 += __shfl_xor_sync(0xffffffffu, lrow0, 1);
    lrow0 += __shfl_xor_sync(0xffffffffu, lrow0, 2);
    lrow1 += __shfl_xor_sync(0xffffffffu, lrow1, 1);
    lrow1 += __shfl_xor_sync(0xffffffffu, lrow1, 2);
    const float inv0 = 1.0f / lrow0;
    const float inv1 = 1.0f / lrow1;

    const int s0 = q0 + wid * 16 + (l >> 2);
    const size_t m0 = (size_t)b * SEQ + s0;
    const size_t m1 = m0 + 8;
#pragma unroll
    for (int nt = 0; nt < 8; nt++) {
        const int c = nt * 8 + 2 * (l & 3);
        const size_t o0 = m0 * KSPLIT + h * HDIM + c;
        const size_t o1 = m1 * KSPLIT + h * HDIM + c;
        {
            const float v0 = oacc[nt][0] * inv0, v1 = oacc[nt][1] * inv0;
            const uint32_t hi = pack_bf16x2(v1, v0);
            const uint32_t lo = pack_bf16x2(v1 - bf16_round(v1), v0 - bf16_round(v0));
            *reinterpret_cast<uint32_t*>(g_Abig + o0)          = hi;
            *reinterpret_cast<uint32_t*>(g_Abig + o0 + DMODEL) = hi;
            *reinterpret_cast<uint32_t*>(g_Abig + o0 + 2 * DMODEL) = lo;
        }
        {
            const float v0 = oacc[nt][2] * inv1, v1 = oacc[nt][3] * inv1;
            const uint32_t hi = pack_bf16x2(v1, v0);
            const uint32_t lo = pack_bf16x2(v1 - bf16_round(v1), v0 - bf16_round(v0));
            *reinterpret_cast<uint32_t*>(g_Abig + o1)          = hi;
            *reinterpret_cast<uint32_t*>(g_Abig + o1 + DMODEL) = hi;
            *reinterpret_cast<uint32_t*>(g_Abig + o1 + 2 * DMODEL) = lo;
        }
    }
}

// ---------------------------------------------------------------------------
extern "C" void kernel_launch(void* const* d_in, const int* in_sizes, int n_in,
                              void* d_out, int out_size)
{
    const float* query = (const float*)d_in[0];
    const float* key   = (const float*)d_in[1];
    const float* value = (const float*)d_in[2];
    const float* Wq    = (const float*)d_in[3];
    const float* bq    = (const float*)d_in[4];
    const float* Wk    = (const float*)d_in[5];
    const float* bk    = (const float*)d_in[6];
    const float* Wv    = (const float*)d_in[7];
    const float* bv    = (const float*)d_in[8];
    const float* Wo    = (const float*)d_in[9];
    const float* bo    = (const float*)d_in[10];
    float* out = (float*)d_out;

    __nv_bfloat16 *pA, *pW, *pQh, *pQl, *pKh, *pKl, *pVh, *pVl;
    cudaGetSymbolAddress((void**)&pA, g_Abig);
    cudaGetSymbolAddress((void**)&pW, g_Wbig);
    cudaGetSymbolAddress((void**)&pQh, g_Qh);
    cudaGetSymbolAddress((void**)&pQl, g_Ql);
    cudaGetSymbolAddress((void**)&pKh, g_Kh);
    cudaGetSymbolAddress((void**)&pKl, g_Kl);
    cudaGetSymbolAddress((void**)&pVh, g_Vh);
    cudaGetSymbolAddress((void**)&pVl, g_Vl);

    cudaFuncSetAttribute(attn_tc, cudaFuncAttributeMaxDynamicSharedMemorySize, 98304);

    const dim3 ggrid(DMODEL / 128, MTOT / 128);   // 8 x 32

    // Q = (query @ Wq^T + bq) * QSCALE -> bf16 hi/lo head layout
    split_kernel<<<MTOT, 256>>>(query, pA, 2);
    split_kernel<<<DMODEL, 256>>>(Wq, pW, 1);
    gemm_hmma<<<ggrid, 256>>>(pA, pW, bq, nullptr, pQh, pQl, QSCALE, 1);

    split_kernel<<<MTOT, 256>>>(key, pA, 2);
    split_kernel<<<DMODEL, 256>>>(Wk, pW, 1);
    gemm_hmma<<<ggrid, 256>>>(pA, pW, bk, nullptr, pKh, pKl, 1.0f, 1);

    split_kernel<<<MTOT, 256>>>(value, pA, 2);
    split_kernel<<<DMODEL, 256>>>(Wv, pW, 1);
    gemm_hmma<<<ggrid, 256>>>(pA, pW, bv, nullptr, pVh, pVl, 1.0f, 1);

    // attention -> writes split A operand for the output projection
    const dim3 agrid(SEQ / 128, HEADS, BATCH);
    attn_tc<<<agrid, 256, 98304>>>();

    // out = O @ Wo^T + bo
    split_kernel<<<DMODEL, 256>>>(Wo, pW, 1);
    gemm_hmma<<<ggrid, 256>>>(pA, pW, bo, out, nullptr, nullptr, 1.0f, 0);
}